// round 7
// baseline (speedup 1.0000x reference)
#include <cuda_runtime.h>
#include <cstdint>
#include <cstddef>

// Problem constants (fixed by the dataset)
#define B_  32
#define N_  1024
#define D_  128
#define C_  16
// P*P = 16, Hg = 32, out image 128x128 per (b,c)

// Warp-autonomous tiling: one warp per 32-row chunk; lane = row.
// 1024 chunks total -> 1024 warps -> 512 CTAs x 64 threads.
#define THREADS 64
#define WARPS_PER_CTA 2

// Static shared (floats):
//   buf  [2][32*128]  per-warp x chunk, XOR-swizzled      (32KB)
//   sw   [16*128]     W, swizzled, staged redundantly     (8KB)
//   tab  [2][272]     per-warp: 256 cbm + 16 masks        (2.1KB)
#define SW_OFF   (WARPS_PER_CTA * 32 * D_)       // 8192
#define TAB_OFF  (SW_OFF + 16 * D_)              // 10240
#define SMEM_FLOATS (TAB_OFF + WARPS_PER_CTA * 272)

// Precomputed channel table: cb[c*16+p] = emb[c]·W[p] + bias[p]
__device__ float g_cb[C_ * 16];

__device__ __forceinline__ uint32_t smem_u32(const void* p) {
    return (uint32_t)__cvta_generic_to_shared(p);
}

// Blackwell packed fp32x2 FMA (PTX-only)
#define FMA_F32X2(d, a, b, c) \
    asm("fma.rn.f32x2 %0, %1, %2, %3;" : "=l"(d) : "l"(a), "l"(b), "l"(c))

// ---------------------------------------------------------------------------
// Kernel A: build the 16x16 channel table once (one warp per entry).
// ---------------------------------------------------------------------------
__global__ void __launch_bounds__(1024, 1)
cb_table_kernel(const float* __restrict__ emb,   // [256, D]
                const float* __restrict__ W,     // [16, D]
                const float* __restrict__ bias)  // [16]
{
    const int w = (blockIdx.x * blockDim.x + threadIdx.x) >> 5;  // 0..255
    const int l = threadIdx.x & 31;
    const int c = w >> 4, p = w & 15;

    float4 e = *reinterpret_cast<const float4*>(emb + (size_t)c * D_ + l * 4);
    float4 v = *reinterpret_cast<const float4*>(W   + (size_t)p * D_ + l * 4);
    float s = e.x * v.x + e.y * v.y + e.z * v.z + e.w * v.w;
    #pragma unroll
    for (int off = 16; off > 0; off >>= 1)
        s += __shfl_xor_sync(0xffffffffu, s, off);
    if (l == 0) g_cb[w] = s + bias[p];
}

// ---------------------------------------------------------------------------
// Kernel B: main fused decode — NO block barriers, warp-autonomous pipeline.
// ---------------------------------------------------------------------------
__global__ void __launch_bounds__(THREADS, 5)
QBD_main_kernel(
    const float* __restrict__ x,     // [B, N, D]
    const float* __restrict__ pmask, // [B, C]
    const float* __restrict__ W,     // [16, D]
    float* __restrict__ out)         // [B, C, 128, 128]
{
    __shared__ float sm[SMEM_FLOATS];
    const int w = threadIdx.x >> 5;
    const int l = threadIdx.x & 31;

    float* buf   = sm + w * (32 * D_);
    float* sw    = sm + SW_OFF;
    float* scbm  = sm + TAB_OFF + w * 272;
    float* smask = scbm + 256;

    const int chunk = blockIdx.x * WARPS_PER_CTA + w;   // 0..1023
    const int b     = chunk >> 5;                       // batch
    const int hg    = chunk & 31;                       // row-group of the image

    // ---- Stage this warp's 32 x-rows (16KB, contiguous) via its own cp.async
    //      group. Swizzle: phys 16B-chunk col = c ^ (row & 7). One warp-instr
    //      per row; lanes = cols (coalesced 512B, conflict-free smem banks). ----
    const float4* gx = reinterpret_cast<const float4*>(
        x + ((size_t)b * N_ + (size_t)hg * 32) * D_);
    #pragma unroll
    for (int i = 0; i < 32; ++i) {
        uint32_t dst = smem_u32(buf + i * D_ + ((l ^ (i & 7)) << 2));
        asm volatile("cp.async.cg.shared.global [%0], [%1], 16;\n"
                     :: "r"(dst), "l"(gx + i * 32 + l));
    }
    // ---- Stage W (8KB) redundantly per warp into the SHARED W buffer
    //      (same values from both warps: benign; own group covers own writes). ----
    const float4* gw = reinterpret_cast<const float4*>(W);
    #pragma unroll
    for (int i = 0; i < 16; ++i) {
        uint32_t dst = smem_u32(sw + i * D_ + ((l ^ (i & 7)) << 2));
        asm volatile("cp.async.cg.shared.global [%0], [%1], 16;\n"
                     :: "r"(dst), "l"(gw + i * 32 + l));
    }
    asm volatile("cp.async.commit_group;\n");

    // ---- Per-warp mask-premultiplied channel table (overlaps DRAM flight) ----
    #pragma unroll
    for (int i = 0; i < 8; ++i) {
        int idx = i * 32 + l;                       // coalesced g_cb read
        scbm[idx] = g_cb[idx] * pmask[b * C_ + (idx >> 4)];
    }
    if (l < C_) smask[l] = pmask[b * C_ + l];

    // ---- Wait ONLY for this warp's copies; warp-local visibility ----
    asm volatile("cp.async.wait_group 0;\n");
    __syncwarp();

    // ---- Main dot products: lane = row, 16 packed accumulators (all p's).
    //      xv: 4-phase floor, conflict-free (swizzle keys 0..7 per 8 lanes);
    //      wv: warp-uniform -> broadcast, 1 phase each. ----
    const float* xr = buf + l * D_;
    const int    xs = l & 7;

    unsigned long long acc2[16];
    #pragma unroll
    for (int j = 0; j < 16; ++j) acc2[j] = 0ull;

    #pragma unroll
    for (int d4 = 0; d4 < 32; ++d4) {
        ulonglong2 xv = *reinterpret_cast<const ulonglong2*>(xr + ((d4 ^ xs) << 2));
        #pragma unroll
        for (int j = 0; j < 16; ++j) {
            const ulonglong2 wv = *reinterpret_cast<const ulonglong2*>(
                sw + j * D_ + ((d4 ^ (j & 7)) << 2));
            FMA_F32X2(acc2[j], xv.x, wv.x, acc2[j]);
            FMA_F32X2(acc2[j], xv.y, wv.y, acc2[j]);
        }
    }

    // ---- Horizontal add (even+odd d), re-pack pairs for packed epilogue ----
    float xa[16];
    #pragma unroll
    for (int j = 0; j < 16; ++j) {
        uint32_t lo, hi;
        asm("mov.b64 {%0, %1}, %2;" : "=r"(lo), "=r"(hi) : "l"(acc2[j]));
        xa[j] = __uint_as_float(lo) + __uint_as_float(hi);
    }
    unsigned long long xa2[8];
    #pragma unroll
    for (int k = 0; k < 8; ++k)
        asm("mov.b64 %0, {%1, %2};" : "=l"(xa2[k])
            : "r"(__float_as_uint(xa[2 * k])), "r"(__float_as_uint(xa[2 * k + 1])));

    // ---- Epilogue: out[b][c][hg*4+pr][l*4+pc] = xa[pr*4+pc]*m_c + cb[c][...]
    //      Lane = wg -> every warp STG.128 is one contiguous 512B line. ----
    float* ob = out + (size_t)b * (C_ * 128 * 128) + hg * 4 * 128 + l * 4;

    #pragma unroll
    for (int c = 0; c < C_; ++c) {
        float m = smask[c];
        unsigned long long m2;
        asm("mov.b64 %0, {%1, %1};" : "=l"(m2) : "r"(__float_as_uint(m)));
        float* oc = ob + c * (128 * 128);
        #pragma unroll
        for (int pr = 0; pr < 4; ++pr) {
            ulonglong2 cb = *reinterpret_cast<const ulonglong2*>(scbm + c * 16 + pr * 4);
            ulonglong2 v;
            FMA_F32X2(v.x, xa2[pr * 2],     m2, cb.x);
            FMA_F32X2(v.y, xa2[pr * 2 + 1], m2, cb.y);
            *reinterpret_cast<ulonglong2*>(oc + pr * 128) = v;
        }
    }
}

extern "C" void kernel_launch(void* const* d_in, const int* in_sizes, int n_in,
                              void* d_out, int out_size)
{
    const float* x    = (const float*)d_in[0];  // [32,1024,128]
    const float* pm   = (const float*)d_in[1];  // [32,16]
    const float* emb  = (const float*)d_in[2];  // [256,128]
    const float* W    = (const float*)d_in[3];  // [16,128]
    const float* bias = (const float*)d_in[4];  // [16]
    float* out        = (float*)d_out;          // [32,16,128,128]

    // Kernel A: 256-entry channel table (one warp per entry)
    cb_table_kernel<<<8, 1024>>>(emb, W, bias);

    // Kernel B: 512 CTAs x 2 warps = 1024 autonomous warp-chunks
    dim3 grid(B_ * N_ / 32 / WARPS_PER_CTA);   // 512
    QBD_main_kernel<<<grid, THREADS>>>(x, pm, W, out);
}